// round 5
// baseline (speedup 1.0000x reference)
#include <cuda_runtime.h>
#include <cstdint>

// ---------------------------------------------------------------------------
// DeepSeek MoE block: T=4096 tokens, D=2048, H=1408, E=8 experts, top-2.
//   out = x + sum_{k=0,1} w_k * ( silu(x W1[e_k]^T) * (x W3[e_k]^T) ) W2[e_k]^T
// Strategy: gate -> compact per-expert (128-aligned segments) ->
//   grouped GEMM1 (TF32 mma.sync, h = w*silu(u)*v) -> grouped GEMM2 ->
//   deterministic gather-combine with residual.
// ---------------------------------------------------------------------------

#define DD 2048
#define HH 1408
#define EE 8
#define TT 4096
#define BM 128
#define BN 64
#define BK 16
#define MAXTILES 72                 // sum ceil(cnt_e/128) <= 8192/128 + 8
#define SLOTCAP (MAXTILES * BM)     // 9216 padded pair slots

// Static device scratch (allocation-free per harness rules)
__device__ float g_h[(size_t)SLOTCAP * HH];    // ~51.9 MB intermediate h (weight folded in)
__device__ float g_yp[(size_t)SLOTCAP * DD];   // ~75.5 MB per-pair down-proj outputs
__device__ int   g_ptok[SLOTCAP];
__device__ float g_pw[SLOTCAP];
__device__ int   g_counts[EE];
__device__ int   g_cursor[EE];
__device__ int   g_tile_e[MAXTILES];
__device__ int   g_topk_e[TT * 2];
__device__ float g_topk_w[TT * 2];
__device__ int   g_tokpair[TT * 2];

// Round-to-nearest TF32 (critical: truncation would bias products ~5e-4)
__device__ __forceinline__ uint32_t f2tf(float f) {
    uint32_t u;
    asm("cvt.rna.tf32.f32 %0, %1;" : "=r"(u) : "f"(f));
    return u;
}

__device__ __forceinline__ void mma8(float* c, const uint32_t* a, uint32_t b0, uint32_t b1) {
    asm volatile(
        "mma.sync.aligned.m16n8k8.row.col.f32.tf32.tf32.f32 "
        "{%0,%1,%2,%3}, {%4,%5,%6,%7}, {%8,%9}, {%0,%1,%2,%3};\n"
        : "+f"(c[0]), "+f"(c[1]), "+f"(c[2]), "+f"(c[3])
        : "r"(a[0]), "r"(a[1]), "r"(a[2]), "r"(a[3]), "r"(b0), "r"(b1));
}

// ---------------------------------------------------------------------------
__global__ void k_init() {
    int i = blockIdx.x * blockDim.x + threadIdx.x;
    if (i < SLOTCAP) g_ptok[i] = -1;
    if (i < EE) g_counts[i] = 0;
}

// One warp per token: logits over 8 experts, softmax, top-2.
__global__ __launch_bounds__(256) void k_gate(const float* __restrict__ x,
                                              const float* __restrict__ Wg) {
    int w = (blockIdx.x * 256 + threadIdx.x) >> 5;
    int lane = threadIdx.x & 31;
    if (w >= TT) return;
    const float* xr = x + (size_t)w * DD;
    float acc[EE];
#pragma unroll
    for (int e = 0; e < EE; e++) acc[e] = 0.f;
    for (int k = lane; k < DD; k += 32) {
        float xv = xr[k];
#pragma unroll
        for (int e = 0; e < EE; e++) acc[e] += xv * Wg[e * DD + k];
    }
#pragma unroll
    for (int e = 0; e < EE; e++) {
#pragma unroll
        for (int off = 16; off; off >>= 1)
            acc[e] += __shfl_xor_sync(0xffffffffu, acc[e], off);
    }
    if (lane == 0) {
        float mx = acc[0];
#pragma unroll
        for (int e = 1; e < EE; e++) mx = fmaxf(mx, acc[e]);
        float ex[EE], sum = 0.f;
#pragma unroll
        for (int e = 0; e < EE; e++) { ex[e] = __expf(acc[e] - mx); sum += ex[e]; }
        float inv = 1.f / sum;
        int i0 = 0; float p0 = ex[0];
#pragma unroll
        for (int e = 1; e < EE; e++) if (ex[e] > p0) { p0 = ex[e]; i0 = e; }
        int i1 = -1; float p1 = -1.f;
#pragma unroll
        for (int e = 0; e < EE; e++)
            if (e != i0 && ex[e] > p1) { p1 = ex[e]; i1 = e; }
        g_topk_e[2 * w]     = i0; g_topk_w[2 * w]     = p0 * inv;
        g_topk_e[2 * w + 1] = i1; g_topk_w[2 * w + 1] = p1 * inv;
        atomicAdd(&g_counts[i0], 1);
        atomicAdd(&g_counts[i1], 1);
    }
}

// Tiny: 128-aligned segment starts + tile->expert map.
__global__ void k_plan() {
    if (threadIdx.x == 0) {
        int start = 0, nt = 0;
        for (int e = 0; e < EE; e++) {
            g_cursor[e] = start;
            int c = g_counts[e];
            int tiles = (c + BM - 1) / BM;
            for (int i = 0; i < tiles; i++) g_tile_e[nt++] = e;
            start += tiles * BM;
        }
        for (; nt < MAXTILES; nt++) g_tile_e[nt] = -1;
    }
}

__global__ void k_scatter() {
    int t = blockIdx.x * blockDim.x + threadIdx.x;
    if (t >= TT) return;
#pragma unroll
    for (int k = 0; k < 2; k++) {
        int e = g_topk_e[2 * t + k];
        float w = g_topk_w[2 * t + k];
        int slot = atomicAdd(&g_cursor[e], 1);
        g_ptok[slot] = t;
        g_pw[slot] = w;
        g_tokpair[2 * t + k] = slot;
    }
}

// ---------------------------------------------------------------------------
// GEMM1: per m-tile (single expert), U = x W1^T, V = x W3^T over K=D,
// epilogue h = w * silu(U) * V. 128x64x16 tiles, 8 warps (4x2), each warp 32x32.
__global__ __launch_bounds__(256) void k_up(const float* __restrict__ x,
                                            const float* __restrict__ W1,
                                            const float* __restrict__ W3) {
    int tile = blockIdx.y;
    int e = g_tile_e[tile];
    if (e < 0) return;
    int nb = blockIdx.x * BN;
    int slot0 = tile * BM;

    __shared__ uint32_t As[BM][BK + 4];
    __shared__ uint32_t B1s[BN][BK + 4];
    __shared__ uint32_t B3s[BN][BK + 4];

    int tid = threadIdx.x, lane = tid & 31, wid = tid >> 5;
    int wm = (wid & 3) * 32, wn = (wid >> 2) * 32;
    int g = lane >> 2, t4 = lane & 3;

    // staging assignments: A = 512 float4 (2/thread), B1/B3 = 256 float4 (1/thread each)
    int arow0 = tid >> 2,        ac4 = tid & 3;
    int arow1 = 64 + (tid >> 2);
    int tok0 = g_ptok[slot0 + arow0]; if (tok0 < 0) tok0 = 0;
    int tok1 = g_ptok[slot0 + arow1]; if (tok1 < 0) tok1 = 0;
    const float* ap0 = x + (size_t)tok0 * DD + ac4 * 4;
    const float* ap1 = x + (size_t)tok1 * DD + ac4 * 4;
    int brow = tid >> 2, bc4 = tid & 3;
    const float* b1p = W1 + ((size_t)e * HH + nb + brow) * DD + bc4 * 4;
    const float* b3p = W3 + ((size_t)e * HH + nb + brow) * DD + bc4 * 4;

    float acc_u[2][4][4], acc_v[2][4][4];
#pragma unroll
    for (int mi = 0; mi < 2; mi++)
#pragma unroll
        for (int ni = 0; ni < 4; ni++)
#pragma unroll
            for (int q = 0; q < 4; q++) { acc_u[mi][ni][q] = 0.f; acc_v[mi][ni][q] = 0.f; }

    float4 fa0 = *(const float4*)ap0;
    float4 fa1 = *(const float4*)ap1;
    float4 f1 = *(const float4*)b1p;
    float4 f3 = *(const float4*)b3p;

    for (int k0 = 0; k0 < DD; k0 += BK) {
        uint4 u;
        u.x = f2tf(fa0.x); u.y = f2tf(fa0.y); u.z = f2tf(fa0.z); u.w = f2tf(fa0.w);
        *(uint4*)&As[arow0][ac4 * 4] = u;
        u.x = f2tf(fa1.x); u.y = f2tf(fa1.y); u.z = f2tf(fa1.z); u.w = f2tf(fa1.w);
        *(uint4*)&As[arow1][ac4 * 4] = u;
        u.x = f2tf(f1.x); u.y = f2tf(f1.y); u.z = f2tf(f1.z); u.w = f2tf(f1.w);
        *(uint4*)&B1s[brow][bc4 * 4] = u;
        u.x = f2tf(f3.x); u.y = f2tf(f3.y); u.z = f2tf(f3.z); u.w = f2tf(f3.w);
        *(uint4*)&B3s[brow][bc4 * 4] = u;
        __syncthreads();

        int kn = k0 + BK;
        if (kn < DD) {   // prefetch next tile; overlaps with compute below
            fa0 = *(const float4*)(ap0 + kn);
            fa1 = *(const float4*)(ap1 + kn);
            f1 = *(const float4*)(b1p + kn);
            f3 = *(const float4*)(b3p + kn);
        }

#pragma unroll
        for (int h = 0; h < 2; h++) {
            uint32_t a[2][4];
#pragma unroll
            for (int mi = 0; mi < 2; mi++) {
                int r = wm + mi * 16 + g;
                a[mi][0] = As[r][h * 8 + t4];
                a[mi][1] = As[r + 8][h * 8 + t4];
                a[mi][2] = As[r][h * 8 + t4 + 4];
                a[mi][3] = As[r + 8][h * 8 + t4 + 4];
            }
#pragma unroll
            for (int ni = 0; ni < 4; ni++) {
                int rn = wn + ni * 8 + g;
                uint32_t bu0 = B1s[rn][h * 8 + t4], bu1 = B1s[rn][h * 8 + t4 + 4];
                uint32_t bv0 = B3s[rn][h * 8 + t4], bv1 = B3s[rn][h * 8 + t4 + 4];
#pragma unroll
                for (int mi = 0; mi < 2; mi++) {
                    mma8(acc_u[mi][ni], a[mi], bu0, bu1);
                    mma8(acc_v[mi][ni], a[mi], bv0, bv1);
                }
            }
        }
        __syncthreads();
    }

    // epilogue: h = w * silu(u) * v
#pragma unroll
    for (int mi = 0; mi < 2; mi++) {
#pragma unroll
        for (int r = 0; r < 2; r++) {
            int m = wm + mi * 16 + r * 8 + g;
            int slot = slot0 + m;
            int tok = g_ptok[slot];
            if (tok < 0) continue;
            float w = g_pw[slot];
            float* hrow = g_h + (size_t)slot * HH + nb + wn;
#pragma unroll
            for (int ni = 0; ni < 4; ni++) {
#pragma unroll
                for (int c = 0; c < 2; c++) {
                    float uu = acc_u[mi][ni][r * 2 + c];
                    float vv = acc_v[mi][ni][r * 2 + c];
                    float s = uu / (1.f + __expf(-uu));
                    hrow[ni * 8 + t4 * 2 + c] = w * s * vv;
                }
            }
        }
    }
}

// GEMM2: y_pair = h W2^T over K=H.
__global__ __launch_bounds__(256) void k_down(const float* __restrict__ W2) {
    int tile = blockIdx.y;
    int e = g_tile_e[tile];
    if (e < 0) return;
    int nb = blockIdx.x * BN;
    int slot0 = tile * BM;

    __shared__ uint32_t As[BM][BK + 4];
    __shared__ uint32_t Bs[BN][BK + 4];

    int tid = threadIdx.x, lane = tid & 31, wid = tid >> 5;
    int wm = (wid & 3) * 32, wn = (wid >> 2) * 32;
    int g = lane >> 2, t4 = lane & 3;

    int arow0 = tid >> 2, ac4 = tid & 3;
    int arow1 = 64 + (tid >> 2);
    const float* ap0 = g_h + (size_t)(slot0 + arow0) * HH + ac4 * 4;
    const float* ap1 = g_h + (size_t)(slot0 + arow1) * HH + ac4 * 4;
    int brow = tid >> 2, bc4 = tid & 3;
    const float* bp = W2 + ((size_t)e * DD + nb + brow) * HH + bc4 * 4;

    float acc[2][4][4];
#pragma unroll
    for (int mi = 0; mi < 2; mi++)
#pragma unroll
        for (int ni = 0; ni < 4; ni++)
#pragma unroll
            for (int q = 0; q < 4; q++) acc[mi][ni][q] = 0.f;

    float4 fa0 = *(const float4*)ap0;
    float4 fa1 = *(const float4*)ap1;
    float4 fb = *(const float4*)bp;

    for (int k0 = 0; k0 < HH; k0 += BK) {
        uint4 u;
        u.x = f2tf(fa0.x); u.y = f2tf(fa0.y); u.z = f2tf(fa0.z); u.w = f2tf(fa0.w);
        *(uint4*)&As[arow0][ac4 * 4] = u;
        u.x = f2tf(fa1.x); u.y = f2tf(fa1.y); u.z = f2tf(fa1.z); u.w = f2tf(fa1.w);
        *(uint4*)&As[arow1][ac4 * 4] = u;
        u.x = f2tf(fb.x); u.y = f2tf(fb.y); u.z = f2tf(fb.z); u.w = f2tf(fb.w);
        *(uint4*)&Bs[brow][bc4 * 4] = u;
        __syncthreads();

        int kn = k0 + BK;
        if (kn < HH) {
            fa0 = *(const float4*)(ap0 + kn);
            fa1 = *(const float4*)(ap1 + kn);
            fb = *(const float4*)(bp + kn);
        }

#pragma unroll
        for (int h = 0; h < 2; h++) {
            uint32_t a[2][4];
#pragma unroll
            for (int mi = 0; mi < 2; mi++) {
                int r = wm + mi * 16 + g;
                a[mi][0] = As[r][h * 8 + t4];
                a[mi][1] = As[r + 8][h * 8 + t4];
                a[mi][2] = As[r][h * 8 + t4 + 4];
                a[mi][3] = As[r + 8][h * 8 + t4 + 4];
            }
#pragma unroll
            for (int ni = 0; ni < 4; ni++) {
                int rn = wn + ni * 8 + g;
                uint32_t b0 = Bs[rn][h * 8 + t4], b1 = Bs[rn][h * 8 + t4 + 4];
#pragma unroll
                for (int mi = 0; mi < 2; mi++) mma8(acc[mi][ni], a[mi], b0, b1);
            }
        }
        __syncthreads();
    }

#pragma unroll
    for (int mi = 0; mi < 2; mi++) {
#pragma unroll
        for (int r = 0; r < 2; r++) {
            int m = wm + mi * 16 + r * 8 + g;
            int slot = slot0 + m;
            if (g_ptok[slot] < 0) continue;
            float* yrow = g_yp + (size_t)slot * DD + nb + wn;
#pragma unroll
            for (int ni = 0; ni < 4; ni++) {
#pragma unroll
                for (int c = 0; c < 2; c++)
                    yrow[ni * 8 + t4 * 2 + c] = acc[mi][ni][r * 2 + c];
            }
        }
    }
}

// out[t] = x[t] + y_pair[p0(t)] + y_pair[p1(t)]  (deterministic gather)
__global__ __launch_bounds__(512) void k_combine(const float* __restrict__ x,
                                                 float* __restrict__ out) {
    int t = blockIdx.x;
    int d = threadIdx.x * 4;
    int s0 = g_tokpair[2 * t], s1 = g_tokpair[2 * t + 1];
    float4 xv = *(const float4*)(x + (size_t)t * DD + d);
    float4 a = *(const float4*)(g_yp + (size_t)s0 * DD + d);
    float4 b = *(const float4*)(g_yp + (size_t)s1 * DD + d);
    float4 o;
    o.x = xv.x + a.x + b.x;
    o.y = xv.y + a.y + b.y;
    o.z = xv.z + a.z + b.z;
    o.w = xv.w + a.w + b.w;
    *(float4*)(out + (size_t)t * DD + d) = o;
}

// ---------------------------------------------------------------------------
extern "C" void kernel_launch(void* const* d_in, const int* in_sizes, int n_in,
                              void* d_out, int out_size) {
    const float* x  = (const float*)d_in[0];
    const float* Wg = (const float*)d_in[1];
    const float* W1 = (const float*)d_in[2];
    const float* W3 = (const float*)d_in[3];
    const float* W2 = (const float*)d_in[4];
    float* out = (float*)d_out;

    k_init<<<(SLOTCAP + 255) / 256, 256>>>();
    k_gate<<<(TT * 32 + 255) / 256, 256>>>(x, Wg);
    k_plan<<<1, 32>>>();
    k_scatter<<<(TT + 255) / 256, 256>>>();
    k_up<<<dim3(HH / BN, MAXTILES), 256>>>(x, W1, W3);
    k_down<<<dim3(DD / BN, MAXTILES), 256>>>(W2);
    k_combine<<<TT, DD / 4>>>(x, out);
}